// round 5
// baseline (speedup 1.0000x reference)
#include <cuda_runtime.h>
#include <cuda_bf16.h>
#include <cstdint>

#define CORES   512
#define SLOTS   4
#define SLEN    64
#define PER_CORE (SLOTS * SLEN)          // 256
#define NSLOTS  (CORES * SLOTS)          // 2048 slots per layer
#define VEC_N   (CORES * PER_CORE)       // 131072
#define C_ENTRIES (CORES * SLOTS * CORES * SLOTS)
#define LIST_CAP 8
#define TASKS_PER_CORE 8                 // 32-row tasks
#define NTASKS  (CORES * TASKS_PER_CORE) // 4096
#define GRID_MV 592                      // 148 SMs x 4 CTAs (one full wave)

// Scratch (__device__ globals; no allocation allowed)
__device__ float g_y1[VEC_N];
__device__ int   g_cnt[2 * NSLOTS];
__device__ int2  g_list[2 * NSLOTS * LIST_CAP];
__device__ int   g_task[2];              // work-stealing counters (per layer)

// ---------------------------------------------------------------------------
__global__ void zero_cnt_kernel(int* __restrict__ cnt, int* __restrict__ task) {
    int i = blockIdx.x * blockDim.x + threadIdx.x;
    if (i < 2 * NSLOTS) cnt[i] = 0;
    if (i < 2) task[i] = 0;
}

// ---------------------------------------------------------------------------
// Compact both routing tensors in one launch.
// C layout [I,J,K,L]: q = ij*512 + k indexes a float4 over l.
// ---------------------------------------------------------------------------
__global__ void compact_kernel(const float4* __restrict__ C1,
                               const float4* __restrict__ C2,
                               int* __restrict__ cnt,
                               int2* __restrict__ lst) {
    const int n4 = C_ENTRIES / 4;           // per tensor
    int g = blockIdx.x * blockDim.x + threadIdx.x;
    int half = gridDim.x * blockDim.x / 2;
    const float4* C = (g < half) ? C1 : C2;
    int* cn  = (g < half) ? cnt : cnt + NSLOTS;
    int2* ls = (g < half) ? lst : lst + NSLOTS * LIST_CAP;
    int base = (g < half) ? g : g - half;
    int stride = half;
    for (int q = base; q < n4; q += stride) {
        float4 v = __ldcs(&C[q]);
        int ij = q >> 9;
        int k  = q & 511;
        float vals[4] = {v.x, v.y, v.z, v.w};
#pragma unroll
        for (int l = 0; l < 4; l++) {
            if (vals[l] != 0.0f) {
                int s = k * 4 + l;
                int pos = atomicAdd(&cn[s], 1);
                if (pos < LIST_CAP)
                    ls[s * LIST_CAP + pos] = make_int2(ij, __float_as_int(vals[l]));
            }
        }
    }
}

// ---------------------------------------------------------------------------
// Fused dispatch-gather + per-core matvec + capped ReLU, fine-grain stealing.
// Task = 32 rows of one core (core = t>>3, rbase = (t&7)*32).
// Per task: gather full 256-elem h into smem (L2-hot loads), then each of
// the 8 warps handles one 4-row group: lanes split (sub = lane>>3 -> row,
// lg = lane&7 -> 128B column chunk); 8 coalesced LDG.128 per warp,
// 3-level shfl reduce within 8-lane groups.
// W per-core layout [j,k,l,m]: row r=(j,l) stride j:16384 l:64; col c=(k,m).
// ---------------------------------------------------------------------------
__global__ void __launch_bounds__(256) fused_mv_kernel(
        const float* __restrict__ W,
        const int*  __restrict__ cnt,
        const int2* __restrict__ lst,
        const float* __restrict__ src,
        float* __restrict__ y,
        int* __restrict__ task_ctr) {
    __shared__ float hs[PER_CORE];
    __shared__ int s_task;
    const int tid  = threadIdx.x;
    const int warp = tid >> 5, lane = tid & 31;
    const int lg  = lane & 7;    // column-chunk index
    const int sub = lane >> 3;   // row within group of 4

    for (;;) {
        if (tid == 0) s_task = atomicAdd(task_ctr, 1);
        __syncthreads();                    // publishes s_task, protects hs reuse
        const int task = s_task;
        if (task >= NTASKS) return;
        const int core  = task >> 3;
        const int rbase = (task & 7) * 32;  // 32-row slice

        // --- gather h for this core (256 threads <-> 256 elements) ---
        {
            int s = core * SLOTS + (tid >> 6);
            int m = tid & 63;
            int n = cnt[s];
            if (n > LIST_CAP) n = LIST_CAP;
            float acc = 0.0f;
#pragma unroll 4
            for (int e = 0; e < n; e++) {
                int2 ent = lst[s * LIST_CAP + e];
                acc += __int_as_float(ent.y) * src[ent.x * SLEN + m];
            }
            hs[tid] = acc;
        }
        __syncthreads();

        // Preload this lane's 8 h-chunks into registers
        float4 hv[8];
#pragma unroll
        for (int t = 0; t < 8; t++)
            hv[t] = reinterpret_cast<const float4*>(hs)[lg + 8 * t];

        const float* Wc = W + (size_t)core * (PER_CORE * PER_CORE);

        // One 4-row group per warp
        {
            int r = rbase + warp * 4 + sub;
            int j = r >> 6, l = r & 63;
            const float* rb = Wc + j * 16384 + l * 64;
            float acc = 0.0f;
#pragma unroll
            for (int t = 0; t < 8; t++) {
                int c = 4 * lg + 32 * t;
                float4 w = __ldcs(reinterpret_cast<const float4*>(
                                      rb + (c >> 6) * 4096 + (c & 63)));
                acc += w.x * hv[t].x + w.y * hv[t].y + w.z * hv[t].z + w.w * hv[t].w;
            }
            acc += __shfl_xor_sync(0xffffffffu, acc, 1);
            acc += __shfl_xor_sync(0xffffffffu, acc, 2);
            acc += __shfl_xor_sync(0xffffffffu, acc, 4);
            if (lg == 0)
                y[core * PER_CORE + r] = fminf(fmaxf(acc, 0.0f), 10.0f);
        }
    }
}

// ---------------------------------------------------------------------------
extern "C" void kernel_launch(void* const* d_in, const int* in_sizes, int n_in,
                              void* d_out, int out_size) {
    const float* x  = (const float*)d_in[0];
    const float* Wi = (const float*)d_in[1];
    const float* Wo = (const float*)d_in[2];
    const float* Ci = (const float*)d_in[3];
    const float* Cc = (const float*)d_in[4];
    float* out = (float*)d_out;

    float* y1;  cudaGetSymbolAddress((void**)&y1,  g_y1);
    int*   cnt; cudaGetSymbolAddress((void**)&cnt, g_cnt);
    int2*  lst; cudaGetSymbolAddress((void**)&lst, g_list);
    int*   tsk; cudaGetSymbolAddress((void**)&tsk, g_task);

    zero_cnt_kernel<<<(2 * NSLOTS + 255) / 256, 256>>>(cnt, tsk);

    compact_kernel<<<4096, 256>>>((const float4*)Ci, (const float4*)Cc,
                                  cnt, lst);

    // Layer 1: dispatch(x)+matvec(Wi) -> y1
    fused_mv_kernel<<<GRID_MV, 256>>>(Wi, cnt, lst, x, y1, tsk);

    // Layer 2: dispatch(y1)+matvec(Wo) -> out
    fused_mv_kernel<<<GRID_MV, 256>>>(Wo, cnt + NSLOTS,
                                      lst + NSLOTS * LIST_CAP, y1, out,
                                      tsk + 1);
}